// round 14
// baseline (speedup 1.0000x reference)
#include <cuda_runtime.h>

#define NBATCH 4
#define NTOK   4096
#define DDIM   16
#define NB     64                    /* bins */
#define XLO    (-6.0f)
#define BINW   0.1875f               /* 12/64, exact in fp32 */
#define INVW   (64.0f / 12.0f)
#define L2E    1.44269504088896f
#define HBLK   4                     /* hist blocks per batch (16 total: co-resident) */
#define HTHR   256                   /* hist threads: 1024 values/block, float4 each */
#define VPB    (NTOK / HBLK)         /* 1024 values per hist block */
#define GX     32                    /* main blocks per batch */
#define NTHR2  256                   /* main kernel: 2 threads per row */
#define RPB    (NTOK / GX)           /* 128 rows per main block */

// Per-(batch,slot) partial moment histograms, written (not accumulated) by k1.
// Layout per slot: 128 float4 — [0..63] = (n,M1,M2,M3), [64..127] = (M4,M5,0,0).
__device__ float4 g_part[NBATCH][HBLK][2 * NB];

__device__ __forceinline__ float ex2f(float v) {
    float r;
    asm("ex2.approx.ftz.f32 %0, %1;" : "=f"(r) : "f"(v));
    return r;
}

// ---------------- kernel 1: per-block partial histograms (1024 values each) ----------------
// Only 16 CTAs -> co-resides with main_kernel's 128 CTAs (144 <= 148 SMs).
__global__ __launch_bounds__(HTHR, 1)
void hist_kernel(const float* __restrict__ x)
{
    __shared__ float h[6][NB];

    const int b   = blockIdx.y;
    const int blk = blockIdx.x;
    const int tid = threadIdx.x;

    // load this thread's float4 early (overlaps zero-fill)
    const float4 vv = reinterpret_cast<const float4*>(x + b * NTOK + blk * VPB)[tid];

    #pragma unroll
    for (int i = tid; i < 6 * NB; i += HTHR)
        (&h[0][0])[i] = 0.f;
    __syncthreads();

    #pragma unroll
    for (int j = 0; j < 4; j++) {
        float v = (j == 0) ? vv.x : (j == 1) ? vv.y : (j == 2) ? vv.z : vv.w;
        int k = __float2int_rz((v - XLO) * INVW);
        k = max(0, min(NB - 1, k));
        float bc = fmaf((float)k + 0.5f, BINW, XLO);
        float d  = v - bc;
        float d2 = d * d;
        float d3 = d2 * d;
        atomicAdd(&h[0][k], 1.0f);
        atomicAdd(&h[1][k], d);
        atomicAdd(&h[2][k], d2);
        atomicAdd(&h[3][k], d3);
        atomicAdd(&h[4][k], d2 * d2);
        atomicAdd(&h[5][k], d3 * d2);
    }
    __syncthreads();

    // write the 2KB partial to this block's private slot (plain stores)
    if (tid < 2 * NB) {
        float4 v4;
        if (tid < NB)
            v4 = make_float4(h[0][tid], h[1][tid], h[2][tid], h[3][tid]);
        else
            v4 = make_float4(h[4][tid - NB], h[5][tid - NB], 0.f, 0.f);
        g_part[b][blk][tid] = v4;
    }

    // make stores visible, then release the dependent launch
    __threadfence();
    cudaTriggerProgrammaticLaunchCompletion();
}

// ---------------- kernel 2: sum partials + per-row softmax-weighted sums ----------------
// Launched with PDL; fully co-resident with hist, so the preamble genuinely overlaps.
__global__ __launch_bounds__(NTHR2, 1)
void main_kernel(const float* __restrict__ x,
                 const float* __restrict__ wq,
                 const float* __restrict__ wk,
                 const float* __restrict__ wv,
                 const float* __restrict__ wo,
                 float* __restrict__ out)
{
    __shared__ float4 shp[2][2 * NB];    // per-half partial column sums
    __shared__ float4 sha[NB];           // (n, M1, M2, M3)
    __shared__ float4 shb[NB];           // (M4, M5, -, -)
    __shared__ float  sr0[NTHR2];        // phase-C partial s0
    __shared__ float  sr1[NTHR2];        // phase-C partial s1

    const int b    = blockIdx.y;
    const int blk  = blockIdx.x;
    const int tid  = threadIdx.x;
    const int col  = tid & 127;          // histogram column / row index
    const int half = tid >> 7;           // 0 or 1

    // ======== PRE-SYNC: everything independent of g_part ========

    const float v = x[b * NTOK + blk * RPB + col];

    float c = 0.f, g = 0.f;
    #pragma unroll
    for (int i = 0; i < DDIM; i++) {
        c = fmaf(wq[i], wk[i], c);
        g = fmaf(wv[i], wo[i], g);
    }
    c *= 0.25f;   // 1/sqrt(ATTN_DIM), TAU = 1

    const float t  = c * v;
    const float u2 = 0.5f * t * t;
    const float u3 = u2 * t * (1.f / 3.f);
    const float u4 = u3 * t * 0.25f;
    const float u5 = u4 * t * 0.2f;
    const float A  = t * L2E;
    const float C0 = -fabsf(A) * 6.0f;           // global max-shift: arg <= 0
    const int   k0 = half * (NB / 2);
    float bb0 = fmaf((float)k0 + 0.5f, BINW, XLO);
    float e0v = ex2f(fmaf(A, bb0, C0));
    const float f = ex2f(A * BINW);

    // ======== wait for hist_kernel's g_part stores ========
    cudaGridDependencySynchronize();

    // ---- sum this thread's float4 column across its 2 slots ----
    {
        const int s0i = half * (HBLK / 2);
        float4 p0 = __ldcg(&g_part[b][s0i + 0][col]);
        float4 p1 = __ldcg(&g_part[b][s0i + 1][col]);
        shp[half][col] = make_float4(p0.x + p1.x, p0.y + p1.y,
                                     p0.z + p1.z, p0.w + p1.w);
    }
    __syncthreads();
    if (half == 0) {
        float4 u = shp[0][col], w = shp[1][col];
        float4 a = make_float4(u.x + w.x, u.y + w.y, u.z + w.z, u.w + w.w);
        if (col < NB) sha[col] = a;
        else          shb[col - NB] = a;
    }
    __syncthreads();

    // ---- phase C: each thread handles 32 bins of row 'col' ----
    {
        float e  = e0v;
        float bb = bb0;
        float s0 = 0.f, s1 = 0.f;

        #pragma unroll
        for (int k = 0; k < NB / 2; k++) {
            float4 ma = sha[k0 + k];             // warp-uniform broadcast
            float4 mb = shb[k0 + k];
            float P = fmaf(t,  ma.y, ma.x);
            P       = fmaf(u2, ma.z, P);
            P       = fmaf(u3, ma.w, P);
            P       = fmaf(u4, mb.x, P);
            P       = fmaf(u5, mb.y, P);
            float Q = fmaf(t,  ma.z, ma.y);
            Q       = fmaf(u2, ma.w, Q);
            Q       = fmaf(u3, mb.x, Q);
            Q       = fmaf(u4, mb.y, Q);
            float r = fmaf(bb, P, Q);
            s0 = fmaf(e, P, s0);
            s1 = fmaf(e, r, s1);
            e *= f;
            bb += BINW;
        }

        sr0[tid] = s0;
        sr1[tid] = s1;
    }
    __syncthreads();

    if (half == 0) {
        float S0 = sr0[col] + sr0[col + 128];
        float S1 = sr1[col] + sr1[col + 128];
        out[b * NTOK + blk * RPB + col] = g * S1 / S0;
    }
}

extern "C" void kernel_launch(void* const* d_in, const int* in_sizes, int n_in,
                              void* d_out, int out_size)
{
    const float* x  = (const float*)d_in[0];
    const float* wq = (const float*)d_in[1];
    const float* wk = (const float*)d_in[2];
    const float* wv = (const float*)d_in[3];
    const float* wo = (const float*)d_in[4];
    float* out = (float*)d_out;

    hist_kernel<<<dim3(HBLK, NBATCH), HTHR>>>(x);

    // PDL launch: main starts while hist is in flight (now fully co-resident);
    // its cudaGridDependencySynchronize() gates only the g_part reads.
    cudaLaunchConfig_t cfg = {};
    cfg.gridDim  = dim3(GX, NBATCH);
    cfg.blockDim = dim3(NTHR2);
    cfg.dynamicSmemBytes = 0;
    cfg.stream = 0;
    cudaLaunchAttribute attrs[1];
    attrs[0].id = cudaLaunchAttributeProgrammaticStreamSerialization;
    attrs[0].val.programmaticStreamSerializationAllowed = 1;
    cfg.attrs = attrs;
    cfg.numAttrs = 1;
    cudaLaunchKernelEx(&cfg, main_kernel, x, wq, wk, wv, wo, out);
}

// round 15
// speedup vs baseline: 1.1358x; 1.1358x over previous
#include <cuda_runtime.h>
#include <cstdint>

#define NBATCH 4
#define NTOK   4096
#define DDIM   16
#define NB     64                    /* bins */
#define XLO    (-6.0f)
#define BINW   0.1875f               /* 12/64, exact in fp32 */
#define INVW   (64.0f / 12.0f)
#define L2E    1.44269504088896f
#define CSZ    8                     /* cluster size (CTAs per cluster) */
#define GXB    32                    /* blocks per batch: 4 clusters */
#define NTHR   128                   /* one thread per row */

__device__ __forceinline__ float ex2f(float v) {
    float r;
    asm("ex2.approx.ftz.f32 %0, %1;" : "=f"(r) : "f"(v));
    return r;
}

__device__ __forceinline__ uint32_t smem_addr(const void* p) {
    return (uint32_t)__cvta_generic_to_shared(p);
}

// DSMEM read: map local shared addr into peer CTA 'rank', 128-bit load.
__device__ __forceinline__ float4 dsmem_ld(uint32_t addr, uint32_t rank) {
    uint32_t ra;
    asm("mapa.shared::cluster.u32 %0, %1, %2;" : "=r"(ra) : "r"(addr), "r"(rank));
    float4 v;
    asm volatile("ld.shared::cluster.v4.f32 {%0,%1,%2,%3}, [%4];"
                 : "=f"(v.x), "=f"(v.y), "=f"(v.z), "=f"(v.w) : "r"(ra));
    return v;
}

#define CLUSTER_ARRIVE() asm volatile("barrier.cluster.arrive.aligned;" ::: "memory")
#define CLUSTER_WAIT()   asm volatile("barrier.cluster.wait.aligned;"   ::: "memory")

__global__ __cluster_dims__(CSZ, 1, 1) __launch_bounds__(NTHR, 1)
void attn_cluster_kernel(const float* __restrict__ x,
                         const float* __restrict__ wq,
                         const float* __restrict__ wk,
                         const float* __restrict__ wv,
                         const float* __restrict__ wo,
                         float* __restrict__ out)
{
    __shared__ float  h[6][NB];          // raw per-CTA partial hist
    __shared__ float4 part[2 * NB];      // repacked partial (peer-readable)
    __shared__ float4 summed[16];        // this CTA's 16 summed columns
    __shared__ float4 stage[CSZ][16];    // staging for the 8-peer sum
    __shared__ float4 sha[NB];           // final (n, M1, M2, M3)
    __shared__ float4 shb[NB];           // final (M4, M5, -, -)

    const int b    = blockIdx.y;
    const int tid  = threadIdx.x;
    const int rank = blockIdx.x & (CSZ - 1);       // CTA rank within cluster

    // ---- phase-C row value (early load; overlaps everything below) ----
    const int row = blockIdx.x * NTHR + tid;       // 0..4095 within batch
    const float v = x[b * NTOK + row];

    // ---- hist input: this CTA covers values [rank*512, rank*512+512) ----
    const float4 vv = reinterpret_cast<const float4*>(x + b * NTOK)[rank * NTHR + tid];

    // ---- zero the partial hist ----
    #pragma unroll
    for (int i = tid; i < 6 * NB; i += NTHR)
        (&h[0][0])[i] = 0.f;

    // ---- tiny dot products (redundant per thread, L1 broadcast) ----
    float c = 0.f, g = 0.f;
    #pragma unroll
    for (int i = 0; i < DDIM; i++) {
        c = fmaf(wq[i], wk[i], c);
        g = fmaf(wv[i], wo[i], g);
    }
    c *= 0.25f;   // 1/sqrt(ATTN_DIM), TAU = 1

    __syncthreads();

    // ---- partial moment histogram (spread smem atomics, 512 values) ----
    #pragma unroll
    for (int j = 0; j < 4; j++) {
        float u = (j == 0) ? vv.x : (j == 1) ? vv.y : (j == 2) ? vv.z : vv.w;
        int k = __float2int_rz((u - XLO) * INVW);
        k = max(0, min(NB - 1, k));
        float bc = fmaf((float)k + 0.5f, BINW, XLO);
        float d  = u - bc;
        float d2 = d * d;
        float d3 = d2 * d;
        atomicAdd(&h[0][k], 1.0f);
        atomicAdd(&h[1][k], d);
        atomicAdd(&h[2][k], d2);
        atomicAdd(&h[3][k], d3);
        atomicAdd(&h[4][k], d2 * d2);
        atomicAdd(&h[5][k], d3 * d2);
    }
    __syncthreads();

    // ---- repack into peer-readable float4 layout ----
    if (tid < NB) part[tid] = make_float4(h[0][tid], h[1][tid], h[2][tid], h[3][tid]);
    else          part[tid] = make_float4(h[4][tid - NB], h[5][tid - NB], 0.f, 0.f);

    // ---- cluster sync #1: all partials visible ----
    CLUSTER_ARRIVE();
    CLUSTER_WAIT();

    // ---- distributed sum: this CTA owns columns [rank*16, rank*16+16) ----
    {
        const int peer = tid >> 4;               // 0..7
        const int cc   = tid & 15;               // 0..15
        uint32_t a = smem_addr(&part[rank * 16 + cc]);
        stage[peer][cc] = dsmem_ld(a, (uint32_t)peer);
        __syncthreads();
        if (tid < 16) {
            float4 s = stage[0][tid];
            #pragma unroll
            for (int p = 1; p < CSZ; p++) {
                float4 q = stage[p][tid];
                s.x += q.x; s.y += q.y; s.z += q.z; s.w += q.w;
            }
            summed[tid] = s;
        }
    }

    // ---- cluster sync #2: all summed slices visible ----
    CLUSTER_ARRIVE();
    CLUSTER_WAIT();

    // ---- gather full summed histogram (one float4 per thread) ----
    {
        const int col   = tid;                   // 0..127
        const int owner = col >> 4;
        uint32_t a = smem_addr(&summed[col & 15]);
        float4 s = dsmem_ld(a, (uint32_t)owner);
        if (col < NB) sha[col] = s;
        else          shb[col - NB] = s;
    }
    __syncthreads();

    // arrive now: peers may stop serving our summed[] once everyone gathered;
    // the matching wait is at kernel end (exit safety), off the critical path.
    CLUSTER_ARRIVE();

    // ---- phase C: row-per-thread softmax-weighted sum over 64 bins ----
    {
        const float t  = c * v;
        const float u2 = 0.5f * t * t;
        const float u3 = u2 * t * (1.f / 3.f);
        const float u4 = u3 * t * 0.25f;
        const float u5 = u4 * t * 0.2f;
        const float A  = t * L2E;
        const float C0 = -fabsf(A) * 6.0f;       // global max-shift: arg <= 0

        float e = ex2f(fmaf(A, XLO + 0.5f * BINW, C0));
        const float f = ex2f(A * BINW);

        float s0 = 0.f, s1 = 0.f;
        float bb = XLO + 0.5f * BINW;

        #pragma unroll
        for (int k = 0; k < NB; k++) {
            float4 ma = sha[k];                  // warp-uniform broadcast
            float4 mb = shb[k];
            float P = fmaf(t,  ma.y, ma.x);
            P       = fmaf(u2, ma.z, P);
            P       = fmaf(u3, ma.w, P);
            P       = fmaf(u4, mb.x, P);
            P       = fmaf(u5, mb.y, P);
            float Q = fmaf(t,  ma.z, ma.y);
            Q       = fmaf(u2, ma.w, Q);
            Q       = fmaf(u3, mb.x, Q);
            Q       = fmaf(u4, mb.y, Q);
            float r = fmaf(bb, P, Q);
            s0 = fmaf(e, P, s0);
            s1 = fmaf(e, r, s1);
            e *= f;
            bb += BINW;
        }

        out[b * NTOK + row] = g * s1 / s0;
    }

    // exit safety: don't leave while peers might still read our smem
    CLUSTER_WAIT();
}

extern "C" void kernel_launch(void* const* d_in, const int* in_sizes, int n_in,
                              void* d_out, int out_size)
{
    const float* x  = (const float*)d_in[0];
    const float* wq = (const float*)d_in[1];
    const float* wk = (const float*)d_in[2];
    const float* wv = (const float*)d_in[3];
    const float* wo = (const float*)d_in[4];
    float* out = (float*)d_out;

    attn_cluster_kernel<<<dim3(GXB, NBATCH), NTHR>>>(x, wq, wk, wv, wo, out);
}

// round 16
// speedup vs baseline: 1.5731x; 1.3851x over previous
#include <cuda_runtime.h>

#define NBATCH 4
#define NTOK   4096
#define DDIM   16
#define NB     64                    /* bins */
#define XLO    (-6.0f)
#define BINW   0.1875f               /* 12/64, exact in fp32 */
#define INVW   (64.0f / 12.0f)
#define L2E    1.44269504088896f
#define GX     32                    /* blocks per batch (both kernels) */
#define NTHR   128                   /* hist: one thread per value */
#define NTHR2  256                   /* main: 2 threads per row */
#define RPB    (NTOK / GX)           /* 128 rows per block */
#define NMOM   6
#define HFLT   (NMOM * NB)           /* 384 floats per batch histogram */

// Parity double-buffered FINAL per-batch moment histograms (REDG-accumulated).
// Buffer p is pre-zeroed by the previous same-parity launch.
__device__ float    g_h6[2][NBATCH][HFLT];   // [moment][bin] flattened
__device__ unsigned g_tick_h;                // hist launch-ticket counter
__device__ unsigned g_tick_m;                // main launch-ticket counter

__device__ __forceinline__ float ex2f(float v) {
    float r;
    asm("ex2.approx.ftz.f32 %0, %1;" : "=f"(r) : "f"(v));
    return r;
}

// ---------------- kernel 1: smem partial hist -> global RED.ADD ----------------
__global__ __launch_bounds__(NTHR, 1)
void hist_kernel(const float* __restrict__ x)
{
    __shared__ float h[NMOM][NB];
    __shared__ unsigned s_ticket;

    const int b   = blockIdx.y;
    const int blk = blockIdx.x;
    const int tid = threadIdx.x;

    if (tid == 0) s_ticket = atomicAdd(&g_tick_h, 1u);

    // load this CTA's 128 values early (L2-resident after first replay)
    const float v = x[b * NTOK + blk * RPB + tid];

    #pragma unroll
    for (int i = tid; i < NMOM * NB; i += NTHR)
        (&h[0][0])[i] = 0.f;
    __syncthreads();

    const int p = (int)((s_ticket >> 7) & 1u);   // launch parity (128 CTAs/launch)

    // ---- smem moment histogram: 768 spread lane-atomics (proven fast) ----
    {
        int k = __float2int_rz((v - XLO) * INVW);
        k = max(0, min(NB - 1, k));
        float bc = fmaf((float)k + 0.5f, BINW, XLO);
        float d  = v - bc;
        float d2 = d * d;
        float d3 = d2 * d;
        atomicAdd(&h[0][k], 1.0f);
        atomicAdd(&h[1][k], d);
        atomicAdd(&h[2][k], d2);
        atomicAdd(&h[3][k], d3);
        atomicAdd(&h[4][k], d2 * d2);
        atomicAdd(&h[5][k], d3 * d2);
    }
    __syncthreads();

    // ---- fire-and-forget REDG into the final per-batch accumulator ----
    #pragma unroll
    for (int i = 0; i < HFLT / NTHR; i++) {      // 3 per thread
        int idx = tid + i * NTHR;
        atomicAdd(&g_h6[p][b][idx], (&h[0][0])[idx]);
    }

    // ---- zero the OTHER parity buffer for the next launch (redundant, harmless) ----
    #pragma unroll
    for (int i = 0; i < HFLT / NTHR; i++) {
        int idx = tid + i * NTHR;
        g_h6[1 - p][b][idx] = 0.f;
    }
}

// ---------------- kernel 2: direct histogram load + per-row sums ----------------
__global__ __launch_bounds__(NTHR2, 1)
void main_kernel(const float* __restrict__ x,
                 const float* __restrict__ wq,
                 const float* __restrict__ wk,
                 const float* __restrict__ wv,
                 const float* __restrict__ wo,
                 float* __restrict__ out)
{
    __shared__ float  hh[NMOM][NB];      // raw histogram staged from global
    __shared__ float4 sha[NB];           // (n, M1, M2, M3)
    __shared__ float4 shb[NB];           // (M4, M5, -, -)
    __shared__ float  sr0[NTHR2];        // phase-C partial s0
    __shared__ float  sr1[NTHR2];        // phase-C partial s1
    __shared__ unsigned s_ticket;

    const int b    = blockIdx.y;
    const int blk  = blockIdx.x;
    const int tid  = threadIdx.x;
    const int col  = tid & 127;          // row index within block
    const int half = tid >> 7;           // 0 or 1

    if (tid == 0) s_ticket = atomicAdd(&g_tick_m, 1u);

    // this thread's row value (L2-resident)
    const float v = x[b * NTOK + blk * RPB + col];

    // tiny dot products (redundant per thread, L1 broadcast)
    float c = 0.f, g = 0.f;
    #pragma unroll
    for (int i = 0; i < DDIM; i++) {
        c = fmaf(wq[i], wk[i], c);
        g = fmaf(wv[i], wo[i], g);
    }
    c *= 0.25f;   // 1/sqrt(ATTN_DIM), TAU = 1

    __syncthreads();
    const int p = (int)((s_ticket >> 7) & 1u);   // matches hist parity (lockstep)

    // ---- stage the FINAL histogram: 96 float4 loads, one L2 round-trip ----
    if (tid < HFLT / 4) {
        float4 f = __ldcg(&reinterpret_cast<const float4*>(g_h6[p][b])[tid]);
        reinterpret_cast<float4*>(&hh[0][0])[tid] = f;
    }
    __syncthreads();

    // repack to float4-per-bin for the hot loop
    if (tid < NB)
        sha[tid] = make_float4(hh[0][tid], hh[1][tid], hh[2][tid], hh[3][tid]);
    else if (tid < 2 * NB)
        shb[tid - NB] = make_float4(hh[4][tid - NB], hh[5][tid - NB], 0.f, 0.f);
    __syncthreads();

    // ---- phase C: each thread handles 32 bins of row 'col' ----
    {
        const float t  = c * v;
        const float u2 = 0.5f * t * t;
        const float u3 = u2 * t * (1.f / 3.f);
        const float u4 = u3 * t * 0.25f;
        const float u5 = u4 * t * 0.2f;
        const float A  = t * L2E;
        const float C0 = -fabsf(A) * 6.0f;       // global max-shift: arg <= 0

        const int   k0 = half * (NB / 2);
        float bb = fmaf((float)k0 + 0.5f, BINW, XLO);
        float e  = ex2f(fmaf(A, bb, C0));
        const float f = ex2f(A * BINW);

        float s0 = 0.f, s1 = 0.f;

        #pragma unroll
        for (int k = 0; k < NB / 2; k++) {
            float4 ma = sha[k0 + k];             // warp-uniform broadcast
            float4 mb = shb[k0 + k];
            float P = fmaf(t,  ma.y, ma.x);
            P       = fmaf(u2, ma.z, P);
            P       = fmaf(u3, ma.w, P);
            P       = fmaf(u4, mb.x, P);
            P       = fmaf(u5, mb.y, P);
            float Q = fmaf(t,  ma.z, ma.y);
            Q       = fmaf(u2, ma.w, Q);
            Q       = fmaf(u3, mb.x, Q);
            Q       = fmaf(u4, mb.y, Q);
            float r = fmaf(bb, P, Q);
            s0 = fmaf(e, P, s0);
            s1 = fmaf(e, r, s1);
            e *= f;
            bb += BINW;
        }

        sr0[tid] = s0;
        sr1[tid] = s1;
    }
    __syncthreads();

    if (half == 0) {
        float S0 = sr0[col] + sr0[col + 128];
        float S1 = sr1[col] + sr1[col + 128];
        out[b * NTOK + blk * RPB + col] = g * S1 / S0;
    }
}

extern "C" void kernel_launch(void* const* d_in, const int* in_sizes, int n_in,
                              void* d_out, int out_size)
{
    const float* x  = (const float*)d_in[0];
    const float* wq = (const float*)d_in[1];
    const float* wk = (const float*)d_in[2];
    const float* wv = (const float*)d_in[3];
    const float* wo = (const float*)d_in[4];
    float* out = (float*)d_out;

    hist_kernel<<<dim3(GX, NBATCH), NTHR>>>(x);
    main_kernel<<<dim3(GX, NBATCH), NTHR2>>>(x, wq, wk, wv, wo, out);
}